// round 16
// baseline (speedup 1.0000x reference)
#include <cuda_runtime.h>
#include <cstdint>

// ---------------------------------------------------------------------------
// GCN_35218731827634: 3x (LeakyReLU -> GCNConv). N=100000, E=640000, D=128.
//
// R16 (= R11..R15 resubmit; broker timeouts, never executed):
//  - CSR edge lists padded to even length ({0,0.f} pads) -> aggregate loads
//    edge PAIRS as one aligned 16B record; no odd tail.
//  - GEMM: A and B operands via 2x LDS.128 each (B owns adjacent col quads);
//    Xs row padded to 132 floats for 16B row alignment.
//  - gemm1 at launch #4 (no CSR dependency) so ncu -s5 -c1 captures it.
// ---------------------------------------------------------------------------

#define N_NODES 100000
#define N_EDGES 640000
#define D 128
#define SCAN_B 1024

struct EdgeRec { int src; float w; };   // 8B packed edge record

// scratch (device globals: no allocation allowed)
__device__ float   g_h[(size_t)N_NODES * D];
__device__ float   g_a[(size_t)N_NODES * D];
__device__ float   g_b[(size_t)N_NODES * D];
__device__ float   g_dinv[N_NODES];
__device__ int     g_deg[N_NODES];
__device__ int     g_rowptr[N_NODES + 1];
__device__ int     g_cursor[N_NODES];
__device__ int     g_blocksum[(N_NODES + SCAN_B - 1) / SCAN_B];
__device__ EdgeRec g_edges[N_EDGES + N_NODES];   // + room for pad records
__device__ int     g_is64;             // 1 if edge_index is int64, 0 if int32

__device__ __forceinline__ float* sel_buf(int sel, float* ext) {
    return sel == 0 ? ext : (sel == 1 ? g_a : g_b);
}
__device__ __forceinline__ const float* sel_cbuf(int sel, const float* ext) {
    return sel == 0 ? ext : (sel == 1 ? (const float*)g_a : (const float*)g_b);
}

__device__ __forceinline__ int edge_at(const void* ei, size_t idx, int is64) {
    if (is64) return (int)((const long long*)ei)[idx];
    return ((const int*)ei)[idx];
}

// ------------------------- dtype detect + deg zero -------------------------
__global__ void init_kernel(const void* ei, int n) {
    int i = blockIdx.x * blockDim.x + threadIdx.x;
    if (i < n) g_deg[i] = 0;
    if (i == 0) {
        const unsigned long long* p = (const unsigned long long*)ei;
        int ok = 1;
        for (int k = 0; k < 16; k++)
            if (p[k] >= (unsigned long long)n) ok = 0;
        g_is64 = ok;
    }
}

// ------------------------------ degree -------------------------------------
__global__ void count_deg_kernel(const void* __restrict__ ei, int E) {
    int e = blockIdx.x * blockDim.x + threadIdx.x;
    if (e < E) {
        int is64 = g_is64;
        atomicAdd(&g_deg[edge_at(ei, (size_t)E + e, is64)], 1);
    }
}

// ------------------------------ CSR build ----------------------------------
// exclusive scan of PADDED degrees ((deg+1)&~1) -> rowptr; also dinv from deg.
__global__ __launch_bounds__(SCAN_B) void scan_block_kernel(int n) {
    __shared__ int warp_sums[32];
    int i = blockIdx.x * SCAN_B + threadIdx.x;
    int v = (i < n) ? g_deg[i] : 0;
    int vp = (v + 1) & ~1;                          // padded to even
    int lane = threadIdx.x & 31, wid = threadIdx.x >> 5;

    if (i < n) g_dinv[i] = rsqrtf((float)(v + 1));  // +1 self loop

    int s = vp;
#pragma unroll
    for (int o = 1; o < 32; o <<= 1) {
        int t = __shfl_up_sync(0xffffffffu, s, o);
        if (lane >= o) s += t;
    }
    if (lane == 31) warp_sums[wid] = s;
    __syncthreads();
    if (wid == 0) {
        int ws = warp_sums[lane];
#pragma unroll
        for (int o = 1; o < 32; o <<= 1) {
            int t = __shfl_up_sync(0xffffffffu, ws, o);
            if (lane >= o) ws += t;
        }
        warp_sums[lane] = ws;
    }
    __syncthreads();
    int excl = s - vp + (wid > 0 ? warp_sums[wid - 1] : 0);
    if (i < n) g_rowptr[i] = excl;
    if (threadIdx.x == SCAN_B - 1) g_blocksum[blockIdx.x] = excl + vp;
}

// finalize: add global block offset, init cursor, write pad record for odd
// degree nodes, and rowptr[n] = padded total.
__global__ __launch_bounds__(256) void finalize_rowptr_kernel(int n, int nb) {
    __shared__ int sh[256];
    int t = threadIdx.x;
    int sb = (blockIdx.x * 256) / SCAN_B;   // 256 | 1024 -> whole block same sb
    sh[t] = (t < sb) ? g_blocksum[t] : 0;
    __syncthreads();
#pragma unroll
    for (int o = 128; o > 0; o >>= 1) {
        if (t < o) sh[t] += sh[t + o];
        __syncthreads();
    }
    int off = sh[0];
    int i = blockIdx.x * 256 + t;
    if (i < n) {
        int r = g_rowptr[i] + off;
        g_rowptr[i] = r;
        g_cursor[i] = r;
        int d = g_deg[i];
        if (d & 1) {                        // pad slot: contributes exactly 0
            EdgeRec pad; pad.src = 0; pad.w = 0.f;
            g_edges[r + d] = pad;
        }
        if (i == n - 1) g_rowptr[n] = r + ((d + 1) & ~1);
    }
}

__global__ void fill_csr_kernel(const void* __restrict__ ei, int E) {
    int e = blockIdx.x * blockDim.x + threadIdx.x;
    if (e >= E) return;
    int is64 = g_is64;
    int s = edge_at(ei, e, is64);
    int d = edge_at(ei, (size_t)E + e, is64);
    int pos = atomicAdd(&g_cursor[d], 1);
    EdgeRec r;
    r.src = s;
    r.w = g_dinv[s] * g_dinv[d];
    g_edges[pos] = r;
}

// ------------------------------ GEMM ---------------------------------------
// h = leaky_relu(X) @ W.  TM=64 x TN=128, TK=32; 256 thr; per thread 4 rows x
// 8 cols as adjacent quads {4tx..4tx+3} and {64+4tx..64+4tx+3}.
// FFMA2 mainloop: A via 2x broadcast LDS.128 from duplicated Xs rows
// (16B-aligned, row stride 132 floats), B via 2x conflict-free LDS.128.
#define TM 64
#define TN 128
#define TK 32
#define XS_PITCH 132   // 2*TM + 4 -> 528B rows (16B aligned)

__global__ __launch_bounds__(256) void gemm_act_kernel(
    const float* __restrict__ Xext, int xsel,
    const float* __restrict__ W, int n)
{
    const float* X = sel_cbuf(xsel, Xext);

    __shared__ float Xs[TK][XS_PITCH];   // duplicated pairs {x,x}
    __shared__ float Ws[TK][TN];

    const int tid = threadIdx.x;
    const int tx = tid & 15;           // column-quad group
    const int ty = tid >> 4;           // row group (4 rows)
    const int row0 = blockIdx.x * TM;

    const int xm0 = tid >> 3;                 // X row within tile (slot 0)
    const int xq0 = tid & 7;                  // X float4-in-k   (slot 0)
    const int xm1 = (tid + 256) >> 3;
    const int xq1 = (tid + 256) & 7;
    const int xr0 = row0 + xm0, xr1 = row0 + xm1;

    unsigned long long acc2[4][4];            // [row i][pair j]
#pragma unroll
    for (int i = 0; i < 4; i++)
#pragma unroll
        for (int j = 0; j < 4; j++) acc2[i][j] = 0ull;

    // ---- stage tile 0 ----
    float4 vx0 = make_float4(0.f, 0.f, 0.f, 0.f), vx1 = vx0;
    if (xr0 < n) vx0 = *(const float4*)(X + (size_t)xr0 * D + xq0 * 4);
    if (xr1 < n) vx1 = *(const float4*)(X + (size_t)xr1 * D + xq1 * 4);
    float4 vw[4];
#pragma unroll
    for (int r = 0; r < 4; r++) {
        int idx = tid + 256 * r;
        vw[r] = *(const float4*)(W + (size_t)(idx >> 5) * D + (idx & 31) * 4);
    }

    for (int kt = 0; kt < D; kt += TK) {
        // ---- commit staged tile to smem (leaky-relu on X, duplicated {x,x}) ----
        {
            float c[4];
            c[0] = vx0.x > 0.f ? vx0.x : 0.01f * vx0.x;
            c[1] = vx0.y > 0.f ? vx0.y : 0.01f * vx0.y;
            c[2] = vx0.z > 0.f ? vx0.z : 0.01f * vx0.z;
            c[3] = vx0.w > 0.f ? vx0.w : 0.01f * vx0.w;
#pragma unroll
            for (int q = 0; q < 4; q++)
                *(float2*)&Xs[xq0 * 4 + q][2 * xm0] = make_float2(c[q], c[q]);
            c[0] = vx1.x > 0.f ? vx1.x : 0.01f * vx1.x;
            c[1] = vx1.y > 0.f ? vx1.y : 0.01f * vx1.y;
            c[2] = vx1.z > 0.f ? vx1.z : 0.01f * vx1.z;
            c[3] = vx1.w > 0.f ? vx1.w : 0.01f * vx1.w;
#pragma unroll
            for (int q = 0; q < 4; q++)
                *(float2*)&Xs[xq1 * 4 + q][2 * xm1] = make_float2(c[q], c[q]);
#pragma unroll
            for (int r = 0; r < 4; r++) {
                int idx = tid + 256 * r;
                *(float4*)&Ws[idx >> 5][(idx & 31) * 4] = vw[r];
            }
        }
        __syncthreads();

        // ---- stage NEXT tile (overlaps with FFMA2 block below) ----
        int ktn = kt + TK;
        if (ktn < D) {
            vx0 = make_float4(0.f, 0.f, 0.f, 0.f); vx1 = vx0;
            if (xr0 < n) vx0 = *(const float4*)(X + (size_t)xr0 * D + ktn + xq0 * 4);
            if (xr1 < n) vx1 = *(const float4*)(X + (size_t)xr1 * D + ktn + xq1 * 4);
#pragma unroll
            for (int r = 0; r < 4; r++) {
                int idx = tid + 256 * r;
                vw[r] = *(const float4*)(W + (size_t)(ktn + (idx >> 5)) * D + (idx & 31) * 4);
            }
        }

        // ---- FFMA2 block (A: 2x LDS.128 broadcast, B: 2x LDS.128) ----
#pragma unroll
        for (int k = 0; k < TK; k++) {
            ulonglong2 A01 = *(const ulonglong2*)&Xs[k][8 * ty];       // rows 4ty,4ty+1
            ulonglong2 A23 = *(const ulonglong2*)&Xs[k][8 * ty + 4];   // rows 4ty+2,4ty+3
            ulonglong2 B01 = *(const ulonglong2*)&Ws[k][4 * tx];       // cols 4tx..4tx+3
            ulonglong2 B23 = *(const ulonglong2*)&Ws[k][64 + 4 * tx];  // cols 64+4tx..
            unsigned long long A[4] = {A01.x, A01.y, A23.x, A23.y};
            unsigned long long B[4] = {B01.x, B01.y, B23.x, B23.y};
#pragma unroll
            for (int i = 0; i < 4; i++)
#pragma unroll
                for (int j = 0; j < 4; j++)
                    asm("fma.rn.f32x2 %0, %1, %2, %0;"
                        : "+l"(acc2[i][j]) : "l"(A[i]), "l"(B[j]));
        }
        __syncthreads();
    }

    // ---- epilogue: 2 float4 stores per row (adjacent quads, coalesced) ----
#pragma unroll
    for (int i = 0; i < 4; i++) {
        int grow = row0 + ty * 4 + i;
        if (grow >= n) continue;
        float* hrow = g_h + (size_t)grow * D;
#pragma unroll
        for (int g = 0; g < 2; g++) {
            unsigned lo0, hi0, lo1, hi1;
            asm("mov.b64 {%0,%1}, %2;" : "=r"(lo0), "=r"(hi0) : "l"(acc2[i][2 * g + 0]));
            asm("mov.b64 {%0,%1}, %2;" : "=r"(lo1), "=r"(hi1) : "l"(acc2[i][2 * g + 1]));
            *(float4*)(hrow + 64 * g + 4 * tx) =
                make_float4(__uint_as_float(lo0), __uint_as_float(hi0),
                            __uint_as_float(lo1), __uint_as_float(hi1));
        }
    }
}

// ------------------------------ aggregate ----------------------------------
// HALF-WARP (16 lanes) per node: lane covers float4 slots {lane, lane+16}.
// Edge lists even-length (padded) -> each iter loads ONE 16B record pair.
__global__ __launch_bounds__(256) void aggregate_kernel(
    float* __restrict__ Oext, int osel, const float* __restrict__ bias, int n)
{
    int gid  = blockIdx.x * 256 + threadIdx.x;
    int node = gid >> 4;
    int lane = gid & 15;
    if (node >= n) return;

    float* OUT = sel_buf(osel, Oext);

    int beg = g_rowptr[node];           // even
    int end = g_rowptr[node + 1];       // even
    int np  = (end - beg) >> 1;         // pairs
    float di = g_dinv[node];
    float d2 = di * di;

    const int o0 = lane * 4;
    const int o1 = (lane + 16) * 4;

    float4 bv0 = *(const float4*)(bias + o0);
    float4 bv1 = *(const float4*)(bias + o1);
    const float* hrow = g_h + (size_t)node * D;
    float4 hv0 = *(const float4*)(hrow + o0);
    float4 hv1 = *(const float4*)(hrow + o1);

    float4 a0, a1;
    a0.x = fmaf(hv0.x, d2, bv0.x);
    a0.y = fmaf(hv0.y, d2, bv0.y);
    a0.z = fmaf(hv0.z, d2, bv0.z);
    a0.w = fmaf(hv0.w, d2, bv0.w);
    a1.x = fmaf(hv1.x, d2, bv1.x);
    a1.y = fmaf(hv1.y, d2, bv1.y);
    a1.z = fmaf(hv1.z, d2, bv1.z);
    a1.w = fmaf(hv1.w, d2, bv1.w);

    if (np > 0) {
        const float4* __restrict__ ep = (const float4*)(g_edges + beg);  // 16B aligned
        float4 E0 = __ldg(ep);
        for (int p = 0; p < np; p++) {
            int   s0 = __float_as_int(E0.x);
            float w0 = E0.y;
            int   s1 = __float_as_int(E0.z);
            float w1 = E0.w;
            if (p + 1 < np) E0 = __ldg(ep + p + 1);          // prefetch
            const float* r0 = g_h + (size_t)s0 * D;
            const float* r1 = g_h + (size_t)s1 * D;
            float4 m00 = *(const float4*)(r0 + o0);
            float4 m01 = *(const float4*)(r0 + o1);
            float4 m10 = *(const float4*)(r1 + o0);
            float4 m11 = *(const float4*)(r1 + o1);
            a0.x = fmaf(w0, m00.x, a0.x);
            a0.y = fmaf(w0, m00.y, a0.y);
            a0.z = fmaf(w0, m00.z, a0.z);
            a0.w = fmaf(w0, m00.w, a0.w);
            a1.x = fmaf(w0, m01.x, a1.x);
            a1.y = fmaf(w0, m01.y, a1.y);
            a1.z = fmaf(w0, m01.z, a1.z);
            a1.w = fmaf(w0, m01.w, a1.w);
            a0.x = fmaf(w1, m10.x, a0.x);
            a0.y = fmaf(w1, m10.y, a0.y);
            a0.z = fmaf(w1, m10.z, a0.z);
            a0.w = fmaf(w1, m10.w, a0.w);
            a1.x = fmaf(w1, m11.x, a1.x);
            a1.y = fmaf(w1, m11.y, a1.y);
            a1.z = fmaf(w1, m11.z, a1.z);
            a1.w = fmaf(w1, m11.w, a1.w);
        }
    }

    float* orow = OUT + (size_t)node * D;
    *(float4*)(orow + o0) = a0;
    *(float4*)(orow + o1) = a1;
}

// ---------------------------------------------------------------------------
extern "C" void kernel_launch(void* const* d_in, const int* in_sizes, int n_in,
                              void* d_out, int out_size)
{
    const float* x  = (const float*)d_in[0];
    const void*  ei = d_in[1];               // int64 or int32, detected on device
    const float* W1 = (const float*)d_in[2];
    const float* b1 = (const float*)d_in[3];
    const float* W2 = (const float*)d_in[4];
    const float* b2 = (const float*)d_in[5];
    const float* W3 = (const float*)d_in[6];
    const float* b3 = (const float*)d_in[7];
    float* out = (float*)d_out;

    const int n = in_sizes[0] / D;       // 100000
    const int E = in_sizes[1] / 2;       // 640000
    const int T = 256;
    const int nb = (n + SCAN_B - 1) / SCAN_B;

    const int gemm_blocks = (n + TM - 1) / TM;
    const int agg_blocks = (int)(((long long)n * 16 + T - 1) / T);

    // setup + layer1 GEMM interleaved: gemm1 has no CSR dependency, placed
    // at launch #4 (where ncu -s5 -c1 lands) so the hot kernel gets profiled.
    init_kernel<<<(n + T - 1) / T, T>>>(ei, n);                 // 1
    count_deg_kernel<<<(E + T - 1) / T, T>>>(ei, E);            // 2
    scan_block_kernel<<<nb, SCAN_B>>>(n);                       // 3 (also dinv)
    gemm_act_kernel<<<gemm_blocks, T>>>(x, 0, W1, n);           // 4  x -> g_h
    finalize_rowptr_kernel<<<(n + T - 1) / T, T>>>(n, nb);      // 5
    fill_csr_kernel<<<(E + T - 1) / T, T>>>(ei, E);             // 6

    // layer 1 aggregate: g_h -> g_a
    aggregate_kernel<<<agg_blocks, T>>>(nullptr, 1, b1, n);     // 7

    // layer 2: g_a -> g_b
    gemm_act_kernel<<<gemm_blocks, T>>>(nullptr, 1, W2, n);     // 8
    aggregate_kernel<<<agg_blocks, T>>>(nullptr, 2, b2, n);     // 9

    // layer 3: g_b -> d_out
    gemm_act_kernel<<<gemm_blocks, T>>>(nullptr, 2, W3, n);     // 10
    aggregate_kernel<<<agg_blocks, T>>>(out, 0, b3, n);         // 11
}